// round 1
// baseline (speedup 1.0000x reference)
#include <cuda_runtime.h>
#include <math.h>
#include <stdint.h>

#define N 512
#define N2 (N*N)
#define BATCH 128
#define NMAT 129           // 128 batch matrices + 1 for L0
#define NB 32
#define NPANEL (N/NB)
#define EPSF 1e-7f

// ---------------- device scratch (no allocations allowed) ----------------
__device__ float g_C[4 * N2];                        // planes [a*2+b][i*N+j], 4 MB
__device__ float g_M[(size_t)NMAT * N2 + 64];        // 129 matrices, ~135 MB
__device__ float g_logdet[NMAT];

// ---------------- kernel 1: IPF + plane construction ----------------
// one thread per (i,j): run 10 IPF iterations on the 2x2 block in registers,
// zero diagonal, clip, fold in Wm and 1/(V_i V_j) -> 4 planes of C.
__global__ void k_ipf(const float* __restrict__ W, const float* __restrict__ Vc,
                      const float* __restrict__ Ec) {
    int p = blockIdx.x * blockDim.x + threadIdx.x;   // 0..N2-1
    int i = p >> 9;
    int j = p & (N - 1);

    float4 e4 = reinterpret_cast<const float4*>(Ec)[p];
    float e00 = expf(e4.x), e01 = expf(e4.y), e10 = expf(e4.z), e11 = expf(e4.w);
    float inv = 1.0f / (e00 + e01 + e10 + e11);
    e00 *= inv; e01 *= inv; e10 *= inv; e11 *= inv;

    // V_i, V_j via stable softmax over L=2
    float a0 = Vc[2*i], a1 = Vc[2*i+1];
    float mi = fmaxf(a0, a1);
    float xa0 = expf(a0 - mi), xa1 = expf(a1 - mi);
    float di = 1.0f / (xa0 + xa1);
    float vi0 = xa0 * di, vi1 = xa1 * di;

    float b0 = Vc[2*j], b1 = Vc[2*j+1];
    float mj = fmaxf(b0, b1);
    float xb0 = expf(b0 - mj), xb1 = expf(b1 - mj);
    float dj = 1.0f / (xb0 + xb1);
    float vj0 = xb0 * dj, vj1 = xb1 * dj;

    #pragma unroll
    for (int it = 0; it < 10; it++) {
        float r0 = e00 + e01 + EPSF, r1 = e10 + e11 + EPSF;
        float c0 = e00 + e10 + EPSF, c1 = e01 + e11 + EPSF;
        float f0 = vi0 / r0, f1 = vi1 / r1;
        e00 *= f0; e01 *= f0; e10 *= f1; e11 *= f1;
        float g0 = vj0 / c0, g1 = vj1 / c1;
        e00 *= g0; e10 *= g0; e01 *= g1; e11 *= g1;
        float iv = 1.0f / (e00 + e01 + e10 + e11 + EPSF);
        e00 *= iv; e01 *= iv; e10 *= iv; e11 *= iv;
    }

    float wm = 0.0f;
    if (i != j) {
        float w = (i > j) ? W[i*N + j] : W[j*N + i];
        wm = 1.0f / (1.0f + expf(-w));
    } else {
        e00 = e01 = e10 = e11 = 0.0f;
    }
    e00 = fminf(fmaxf(e00, 0.0f), 1.0f);
    e01 = fminf(fmaxf(e01, 0.0f), 1.0f);
    e10 = fminf(fmaxf(e10, 0.0f), 1.0f);
    e11 = fminf(fmaxf(e11, 0.0f), 1.0f);

    g_C[0*N2 + p] = wm * e00 / (vi0 * vj0);
    g_C[1*N2 + p] = wm * e01 / (vi0 * vj1);
    g_C[2*N2 + p] = wm * e10 / (vi1 * vj0);
    g_C[3*N2 + p] = wm * e11 / (vi1 * vj1);
}

// ---------------- kernel 2: build matrix + blocked LU (no pivoting) ----------------
// One CTA per matrix. Laplacian is strictly row-diagonally-dominant with
// positive diagonal -> GE without pivoting is stable, all pivots > 0.
#define SP_STRIDE 33           // 512 x 33 panel (conflict-free: 33 coprime 32)
#define SU_STRIDE 520          // 32 x 520, multiple of 8 for aligned float4
#define SMEM_LU_BYTES ((N*SP_STRIDE + NB*SU_STRIDE) * 4 + N * 4 + 64)

__global__ void __launch_bounds__(256, 1) k_lu(const int* __restrict__ x,
                                               const float* __restrict__ W) {
    extern __shared__ float smem[];
    float* sP   = smem;                          // panel [r*33 + c], r global row
    float* sU   = smem + N * SP_STRIDE;          // U12  [k*520 + c], c global col
    int*   sx   = (int*)(sU + NB * SU_STRIDE);   // x row for this batch
    float* sacc = (float*)(sx + N);              // logdet accumulator

    const int batch = blockIdx.x;
    const int tid   = threadIdx.x;
    float* Mb = g_M + (size_t)batch * N2;

    if (batch < BATCH) {
        for (int t = tid; t < N; t += 256) sx[t] = x[batch*N + t];
    }
    if (tid == 0) sacc[0] = 0.0f;
    __syncthreads();

    // ---- build the padded 512x512 matrix (rows 0..510 <-> nodes 1..511) ----
    {
        int w = tid >> 5, lane = tid & 31;
        for (int r = w; r < N; r += 8) {
            if (r == N - 1) {                    // identity pad row
                for (int c = lane; c < N; c += 32) Mb[r*N + c] = (c == N-1) ? 1.0f : 0.0f;
                continue;
            }
            int i = r + 1;
            float sum = 0.0f;
            if (batch < BATCH) {
                int xi = sx[i];
                const float* p0 = g_C + (size_t)(xi*2) * N2 + (size_t)i * N;
                const float* p1 = p0 + N2;
                for (int j = lane; j < N; j += 32) {
                    float v0 = p0[j], v1 = p1[j];
                    float v = sx[j] ? v1 : v0;   // C[i,j,x_i,x_j]
                    sum += v;
                    int c = j - 1;
                    if (j > 0 && c != r) Mb[r*N + c] = -v;
                }
            } else {                             // L0 from Wm = sym(tril(sigmoid(W)))
                for (int j = lane; j < N; j += 32) {
                    float v = 0.0f;
                    if (j != i) {
                        float wv = (i > j) ? W[i*N + j] : W[j*N + i];
                        v = 1.0f / (1.0f + expf(-wv));
                    }
                    sum += v;
                    int c = j - 1;
                    if (j > 0 && c != r) Mb[r*N + c] = -v;
                }
            }
            #pragma unroll
            for (int off = 16; off; off >>= 1) sum += __shfl_xor_sync(0xffffffffu, sum, off);
            if (lane == 0) { Mb[r*N + r] = sum; Mb[r*N + (N-1)] = 0.0f; }
        }
    }
    __syncthreads();

    // ---- blocked LU ----
    for (int kb = 0; kb < NPANEL; kb++) {
        int j0 = kb * NB, j1 = j0 + NB;
        int m = N - j0;

        // load panel [rows j0..511, cols j0..j0+31] into SMEM
        for (int e = tid; e < m * NB; e += 256) {
            int rr = j0 + (e >> 5);
            int cc = e & 31;
            sP[rr*SP_STRIDE + cc] = Mb[rr*N + j0 + cc];
        }
        __syncthreads();

        // factor panel (unpivoted)
        for (int j = 0; j < NB; j++) {
            float pinv = 1.0f / sP[(j0+j)*SP_STRIDE + j];
            const float* prow = &sP[(j0+j)*SP_STRIDE];
            for (int r = j0 + j + 1 + tid; r < N; r += 256) {
                float lij = sP[r*SP_STRIDE + j] * pinv;
                sP[r*SP_STRIDE + j] = lij;
                for (int c = j + 1; c < NB; c++)
                    sP[r*SP_STRIDE + c] -= lij * prow[c];
            }
            __syncthreads();
        }

        // accumulate logdet from this panel's diagonal
        if (tid < 32) {
            float v = logf(fabsf(sP[(j0+tid)*SP_STRIDE + tid]));
            #pragma unroll
            for (int off = 16; off; off >>= 1) v += __shfl_xor_sync(0xffffffffu, v, off);
            if (tid == 0) sacc[0] += v;
        }

        if (j1 < N) {
            // U12 = L11^{-1} A12  (forward substitution, fully unrolled)
            for (int c = j1 + tid; c < N; c += 256) {
                float y[NB];
                #pragma unroll
                for (int k = 0; k < NB; k++) y[k] = Mb[(j0+k)*N + c];
                #pragma unroll
                for (int k = 1; k < NB; k++) {
                    float acc = y[k];
                    #pragma unroll
                    for (int t = 0; t < k; t++) acc -= sP[(j0+k)*SP_STRIDE + t] * y[t];
                    y[k] = acc;
                }
                #pragma unroll
                for (int k = 0; k < NB; k++) sU[k*SU_STRIDE + c] = y[k];
            }
            __syncthreads();

            // trailing update: A22 -= L21 * U12   (8x8 register tile / thread)
            for (int rb = j1; rb < N; rb += 128) {
                for (int cb = j1; cb < N; cb += 128) {
                    int tx = tid & 15, ty = tid >> 4;
                    int r0 = rb + ty * 8;
                    int c0 = cb + tx * 8;
                    bool cok = (c0 < N);
                    int c0c = cok ? c0 : j1;
                    int rr[8];
                    #pragma unroll
                    for (int ii = 0; ii < 8; ii++) rr[ii] = min(r0 + ii, N - 1);

                    float acc[8][8];
                    #pragma unroll
                    for (int ii = 0; ii < 8; ii++) {
                        const float4* src = reinterpret_cast<const float4*>(&Mb[rr[ii]*N + c0c]);
                        float4 u0 = src[0], u1 = src[1];
                        acc[ii][0]=u0.x; acc[ii][1]=u0.y; acc[ii][2]=u0.z; acc[ii][3]=u0.w;
                        acc[ii][4]=u1.x; acc[ii][5]=u1.y; acc[ii][6]=u1.z; acc[ii][7]=u1.w;
                    }
                    #pragma unroll 8
                    for (int k = 0; k < NB; k++) {
                        float4 b0 = *reinterpret_cast<const float4*>(&sU[k*SU_STRIDE + c0c]);
                        float4 b1 = *reinterpret_cast<const float4*>(&sU[k*SU_STRIDE + c0c + 4]);
                        float a[8];
                        #pragma unroll
                        for (int ii = 0; ii < 8; ii++) a[ii] = sP[rr[ii]*SP_STRIDE + k];
                        #pragma unroll
                        for (int ii = 0; ii < 8; ii++) {
                            acc[ii][0] -= a[ii]*b0.x; acc[ii][1] -= a[ii]*b0.y;
                            acc[ii][2] -= a[ii]*b0.z; acc[ii][3] -= a[ii]*b0.w;
                            acc[ii][4] -= a[ii]*b1.x; acc[ii][5] -= a[ii]*b1.y;
                            acc[ii][6] -= a[ii]*b1.z; acc[ii][7] -= a[ii]*b1.w;
                        }
                    }
                    #pragma unroll
                    for (int ii = 0; ii < 8; ii++) {
                        if (cok && (r0 + ii) < N) {
                            float4 o0 = make_float4(acc[ii][0], acc[ii][1], acc[ii][2], acc[ii][3]);
                            float4 o1 = make_float4(acc[ii][4], acc[ii][5], acc[ii][6], acc[ii][7]);
                            float4* dst = reinterpret_cast<float4*>(&Mb[(r0+ii)*N + c0]);
                            dst[0] = o0; dst[1] = o1;
                        }
                    }
                }
            }
            __syncthreads();
        }
    }
    __syncthreads();
    if (tid == 0) g_logdet[batch] = sacc[0];
}

// ---------------- kernel 3: combine ----------------
__global__ void k_final(const int* __restrict__ x, const float* __restrict__ Vc,
                        float* __restrict__ out) {
    __shared__ float red[256];
    int b = blockIdx.x, tid = threadIdx.x;
    float s = 0.0f;
    for (int i = tid; i < N; i += 256) {
        int xi = x[b*N + i];
        float a0 = Vc[2*i], a1 = Vc[2*i+1];
        float m = fmaxf(a0, a1);
        float lse = m + logf(expf(a0 - m) + expf(a1 - m));
        s += (xi ? a1 : a0) - lse;
    }
    red[tid] = s;
    __syncthreads();
    #pragma unroll
    for (int o = 128; o; o >>= 1) {
        if (tid < o) red[tid] += red[tid + o];
        __syncthreads();
    }
    if (tid == 0) out[b] = red[0] + g_logdet[b] - g_logdet[BATCH];
}

// ---------------- launcher ----------------
extern "C" void kernel_launch(void* const* d_in, const int* in_sizes, int n_in,
                              void* d_out, int out_size) {
    const int* x = nullptr;
    const float* W = nullptr;
    const float* Vc = nullptr;
    const float* Ec = nullptr;
    for (int k = 0; k < n_in; k++) {
        switch (in_sizes[k]) {
            case BATCH * N:   x  = (const int*)d_in[k];   break;  // 65536
            case N * N:       W  = (const float*)d_in[k]; break;  // 262144
            case N * 2:       Vc = (const float*)d_in[k]; break;  // 1024
            case N * N * 4:   Ec = (const float*)d_in[k]; break;  // 1048576
        }
    }
    float* out = (float*)d_out;

    cudaFuncSetAttribute(k_lu, cudaFuncAttributeMaxDynamicSharedMemorySize, SMEM_LU_BYTES);

    k_ipf<<<N2 / 256, 256>>>(W, Vc, Ec);
    k_lu<<<NMAT, 256, SMEM_LU_BYTES>>>(x, W);
    k_final<<<BATCH, 256>>>(x, Vc, out);
}

// round 2
// speedup vs baseline: 1.4111x; 1.4111x over previous
#include <cuda_runtime.h>
#include <math.h>
#include <stdint.h>

#define N 512
#define N2 (N*N)
#define BATCH 128
#define NMAT 129           // 128 batch matrices + 1 for L0
#define NB 32
#define NPANEL (N/NB)
#define EPSF 1e-7f

typedef unsigned long long u64;

// packed f32x2 FMA (Blackwell FFMA2 — only reachable via PTX)
__device__ __forceinline__ u64 ffma2(u64 a, u64 b, u64 c) {
    u64 d;
    asm("fma.rn.f32x2 %0, %1, %2, %3;" : "=l"(d) : "l"(a), "l"(b), "l"(c));
    return d;
}
__device__ __forceinline__ u64 pack_dup(float a) {
    u64 d; unsigned int u = __float_as_uint(a);
    asm("mov.b64 %0, {%1, %1};" : "=l"(d) : "r"(u));
    return d;
}

// ---------------- device scratch (no allocations allowed) ----------------
__device__ float g_C[4 * N2];                        // planes [a*2+b][i*N+j], 4 MB
__device__ float g_M[(size_t)NMAT * N2 + 64];        // 129 matrices, ~135 MB
__device__ float g_logdet[NMAT];

// ---------------- kernel 1: IPF + plane construction ----------------
__global__ void k_ipf(const float* __restrict__ W, const float* __restrict__ Vc,
                      const float* __restrict__ Ec) {
    int p = blockIdx.x * blockDim.x + threadIdx.x;   // 0..N2-1
    int i = p >> 9;
    int j = p & (N - 1);

    float4 e4 = reinterpret_cast<const float4*>(Ec)[p];
    float e00 = expf(e4.x), e01 = expf(e4.y), e10 = expf(e4.z), e11 = expf(e4.w);
    float inv = 1.0f / (e00 + e01 + e10 + e11);
    e00 *= inv; e01 *= inv; e10 *= inv; e11 *= inv;

    float a0 = Vc[2*i], a1 = Vc[2*i+1];
    float mi = fmaxf(a0, a1);
    float xa0 = expf(a0 - mi), xa1 = expf(a1 - mi);
    float di = 1.0f / (xa0 + xa1);
    float vi0 = xa0 * di, vi1 = xa1 * di;

    float b0 = Vc[2*j], b1 = Vc[2*j+1];
    float mj = fmaxf(b0, b1);
    float xb0 = expf(b0 - mj), xb1 = expf(b1 - mj);
    float dj = 1.0f / (xb0 + xb1);
    float vj0 = xb0 * dj, vj1 = xb1 * dj;

    #pragma unroll
    for (int it = 0; it < 10; it++) {
        float r0 = e00 + e01 + EPSF, r1 = e10 + e11 + EPSF;
        float c0 = e00 + e10 + EPSF, c1 = e01 + e11 + EPSF;
        float f0 = vi0 / r0, f1 = vi1 / r1;
        e00 *= f0; e01 *= f0; e10 *= f1; e11 *= f1;
        float g0 = vj0 / c0, g1 = vj1 / c1;
        e00 *= g0; e10 *= g0; e01 *= g1; e11 *= g1;
        float iv = 1.0f / (e00 + e01 + e10 + e11 + EPSF);
        e00 *= iv; e01 *= iv; e10 *= iv; e11 *= iv;
    }

    float wm = 0.0f;
    if (i != j) {
        float w = (i > j) ? W[i*N + j] : W[j*N + i];
        wm = 1.0f / (1.0f + expf(-w));
    } else {
        e00 = e01 = e10 = e11 = 0.0f;
    }
    e00 = fminf(fmaxf(e00, 0.0f), 1.0f);
    e01 = fminf(fmaxf(e01, 0.0f), 1.0f);
    e10 = fminf(fmaxf(e10, 0.0f), 1.0f);
    e11 = fminf(fmaxf(e11, 0.0f), 1.0f);

    g_C[0*N2 + p] = wm * e00 / (vi0 * vj0);
    g_C[1*N2 + p] = wm * e01 / (vi0 * vj1);
    g_C[2*N2 + p] = wm * e10 / (vi1 * vj0);
    g_C[3*N2 + p] = wm * e11 / (vi1 * vj1);
}

// ---------------- kernel 2: build matrix + blocked LU (no pivoting) ----------------
#define SP_STRIDE 33            // 512 x 33 row-major panel (factorization)
#define SU_STRIDE 520           // 32 x 520 U12 row (c global col), 16B-aligned rows
#define SPT_STRIDE 520          // 32 x 520 transposed, NEGATED L21 (k-major)
#define NTHR 512
#define SMEM_LU_BYTES ((N*SP_STRIDE + NB*SU_STRIDE + NB*SPT_STRIDE) * 4 + N * 4 + 64)

__global__ void __launch_bounds__(NTHR, 1) k_lu(const int* __restrict__ x,
                                                const float* __restrict__ W) {
    extern __shared__ float smem[];
    float* sP   = smem;                           // [r*33 + c], r global row
    float* sU   = sP + N * SP_STRIDE;             // U12  [k*520 + c]
    float* sPT  = sU + NB * SU_STRIDE;            // -L21 [k*520 + r]
    int*   sx   = (int*)(sPT + NB * SPT_STRIDE);
    float* sacc = (float*)(sx + N);

    const int batch = blockIdx.x;
    const int tid   = threadIdx.x;
    float* Mb = g_M + (size_t)batch * N2;

    if (batch < BATCH) {
        for (int t = tid; t < N; t += NTHR) sx[t] = x[batch*N + t];
    }
    if (tid == 0) sacc[0] = 0.0f;
    __syncthreads();

    // ---- build the padded 512x512 matrix (rows 0..510 <-> nodes 1..511) ----
    {
        int w = tid >> 5, lane = tid & 31;
        for (int r = w; r < N; r += 16) {
            if (r == N - 1) {                    // identity pad row
                for (int c = lane; c < N; c += 32) Mb[r*N + c] = (c == N-1) ? 1.0f : 0.0f;
                continue;
            }
            int i = r + 1;
            float sum = 0.0f;
            if (batch < BATCH) {
                int xi = sx[i];
                const float* p0 = g_C + (size_t)(xi*2) * N2 + (size_t)i * N;
                const float* p1 = p0 + N2;
                for (int j = lane; j < N; j += 32) {
                    float v0 = p0[j], v1 = p1[j];
                    float v = sx[j] ? v1 : v0;   // C[i,j,x_i,x_j]
                    sum += v;
                    int c = j - 1;
                    if (j > 0 && c != r) Mb[r*N + c] = -v;
                }
            } else {                             // L0 from Wm = sym(tril(sigmoid(W)))
                for (int j = lane; j < N; j += 32) {
                    float v = 0.0f;
                    if (j != i) {
                        float wv = (i > j) ? W[i*N + j] : W[j*N + i];
                        v = 1.0f / (1.0f + expf(-wv));
                    }
                    sum += v;
                    int c = j - 1;
                    if (j > 0 && c != r) Mb[r*N + c] = -v;
                }
            }
            #pragma unroll
            for (int off = 16; off; off >>= 1) sum += __shfl_xor_sync(0xffffffffu, sum, off);
            if (lane == 0) { Mb[r*N + r] = sum; Mb[r*N + (N-1)] = 0.0f; }
        }
    }
    __syncthreads();

    // ---- blocked LU ----
    for (int kb = 0; kb < NPANEL; kb++) {
        int j0 = kb * NB, j1 = j0 + NB;
        int m = N - j0;

        // load panel [rows j0..511, cols j0..j0+31] into SMEM
        for (int e = tid; e < m * NB; e += NTHR) {
            int rr = j0 + (e >> 5);
            int cc = e & 31;
            sP[rr*SP_STRIDE + cc] = Mb[rr*N + j0 + cc];
        }
        __syncthreads();

        // factor panel (unpivoted; Laplacian diag-dominant => stable, pivots > 0)
        for (int j = 0; j < NB; j++) {
            float pinv = 1.0f / sP[(j0+j)*SP_STRIDE + j];
            const float* prow = &sP[(j0+j)*SP_STRIDE];
            for (int r = j0 + j + 1 + tid; r < N; r += NTHR) {
                float lij = sP[r*SP_STRIDE + j] * pinv;
                sP[r*SP_STRIDE + j] = lij;
                for (int c = j + 1; c < NB; c++)
                    sP[r*SP_STRIDE + c] -= lij * prow[c];
            }
            __syncthreads();
        }

        // accumulate logdet from this panel's diagonal
        if (tid < 32) {
            float v = logf(fabsf(sP[(j0+tid)*SP_STRIDE + tid]));
            #pragma unroll
            for (int off = 16; off; off >>= 1) v += __shfl_xor_sync(0xffffffffu, v, off);
            if (tid == 0) sacc[0] += v;
        }

        if (j1 < N) {
            // transposed, NEGATED L21 copy: sPT[k][r] = -L[r][j0+k]
            // (row-contiguous writes/reads: conflict-free; enables LDS.128 a-loads)
            for (int r = j1 + tid; r < N; r += NTHR) {
                #pragma unroll
                for (int k = 0; k < NB; k++)
                    sPT[k*SPT_STRIDE + r] = -sP[r*SP_STRIDE + k];
            }

            // U12 = L11^{-1} A12  (forward substitution, fully unrolled)
            for (int c = j1 + tid; c < N; c += NTHR) {
                float y[NB];
                #pragma unroll
                for (int k = 0; k < NB; k++) y[k] = Mb[(j0+k)*N + c];
                #pragma unroll
                for (int k = 1; k < NB; k++) {
                    float acc = y[k];
                    #pragma unroll
                    for (int t = 0; t < k; t++) acc -= sP[(j0+k)*SP_STRIDE + t] * y[t];
                    y[k] = acc;
                }
                #pragma unroll
                for (int k = 0; k < NB; k++) sU[k*SU_STRIDE + c] = y[k];
            }
            __syncthreads();

            // trailing update: A22 += (-L21) * U12, 8x8/thread, packed f32x2
            for (int rb = j1; rb < N; rb += 256) {
                for (int cb = j1; cb < N; cb += 128) {
                    int tx = tid & 15, ty = tid >> 4;
                    int r0 = rb + ty * 8;
                    int c0 = cb + tx * 8;
                    if (r0 < N && c0 < N) {
                        u64 acc[8][4];
                        #pragma unroll
                        for (int ii = 0; ii < 8; ii++) {
                            const ulonglong2* src =
                                reinterpret_cast<const ulonglong2*>(&Mb[(r0+ii)*N + c0]);
                            ulonglong2 u0 = src[0], u1 = src[1];
                            acc[ii][0] = u0.x; acc[ii][1] = u0.y;
                            acc[ii][2] = u1.x; acc[ii][3] = u1.y;
                        }
                        #pragma unroll 8
                        for (int k = 0; k < NB; k++) {
                            ulonglong2 b0 = *reinterpret_cast<const ulonglong2*>(
                                &sU[k*SU_STRIDE + c0]);
                            ulonglong2 b1 = *reinterpret_cast<const ulonglong2*>(
                                &sU[k*SU_STRIDE + c0 + 4]);
                            float4 aA = *reinterpret_cast<const float4*>(
                                &sPT[k*SPT_STRIDE + r0]);
                            float4 aB = *reinterpret_cast<const float4*>(
                                &sPT[k*SPT_STRIDE + r0 + 4]);
                            float af[8] = {aA.x, aA.y, aA.z, aA.w, aB.x, aB.y, aB.z, aB.w};
                            #pragma unroll
                            for (int ii = 0; ii < 8; ii++) {
                                u64 a2 = pack_dup(af[ii]);
                                acc[ii][0] = ffma2(a2, b0.x, acc[ii][0]);
                                acc[ii][1] = ffma2(a2, b0.y, acc[ii][1]);
                                acc[ii][2] = ffma2(a2, b1.x, acc[ii][2]);
                                acc[ii][3] = ffma2(a2, b1.y, acc[ii][3]);
                            }
                        }
                        #pragma unroll
                        for (int ii = 0; ii < 8; ii++) {
                            ulonglong2* dst =
                                reinterpret_cast<ulonglong2*>(&Mb[(r0+ii)*N + c0]);
                            ulonglong2 o0, o1;
                            o0.x = acc[ii][0]; o0.y = acc[ii][1];
                            o1.x = acc[ii][2]; o1.y = acc[ii][3];
                            dst[0] = o0; dst[1] = o1;
                        }
                    }
                }
            }
            __syncthreads();
        }
    }
    __syncthreads();
    if (tid == 0) g_logdet[batch] = sacc[0];
}

// ---------------- kernel 3: combine ----------------
__global__ void k_final(const int* __restrict__ x, const float* __restrict__ Vc,
                        float* __restrict__ out) {
    __shared__ float red[256];
    int b = blockIdx.x, tid = threadIdx.x;
    float s = 0.0f;
    for (int i = tid; i < N; i += 256) {
        int xi = x[b*N + i];
        float a0 = Vc[2*i], a1 = Vc[2*i+1];
        float m = fmaxf(a0, a1);
        float lse = m + logf(expf(a0 - m) + expf(a1 - m));
        s += (xi ? a1 : a0) - lse;
    }
    red[tid] = s;
    __syncthreads();
    #pragma unroll
    for (int o = 128; o; o >>= 1) {
        if (tid < o) red[tid] += red[tid + o];
        __syncthreads();
    }
    if (tid == 0) out[b] = red[0] + g_logdet[b] - g_logdet[BATCH];
}

// ---------------- launcher ----------------
extern "C" void kernel_launch(void* const* d_in, const int* in_sizes, int n_in,
                              void* d_out, int out_size) {
    const int* x = nullptr;
    const float* W = nullptr;
    const float* Vc = nullptr;
    const float* Ec = nullptr;
    for (int k = 0; k < n_in; k++) {
        switch (in_sizes[k]) {
            case BATCH * N:   x  = (const int*)d_in[k];   break;  // 65536
            case N * N:       W  = (const float*)d_in[k]; break;  // 262144
            case N * 2:       Vc = (const float*)d_in[k]; break;  // 1024
            case N * N * 4:   Ec = (const float*)d_in[k]; break;  // 1048576
        }
    }
    float* out = (float*)d_out;

    cudaFuncSetAttribute(k_lu, cudaFuncAttributeMaxDynamicSharedMemorySize, SMEM_LU_BYTES);

    k_ipf<<<N2 / 256, 256>>>(W, Vc, Ec);
    k_lu<<<NMAT, NTHR, SMEM_LU_BYTES>>>(x, W);
    k_final<<<BATCH, 256>>>(x, Vc, out);
}